// round 14
// baseline (speedup 1.0000x reference)
#include <cuda_runtime.h>
#include <cuda_fp16.h>
#include <cstdint>

#define BB 32
#define NN 2048
#define MM 2048
#define DD 128

#define NJT_JOB 8         // j-tiles per job (half sweep)

// fp16 tiles in smem: 128 rows x 128 halfs, row stride 272 bytes (16B pad)
#define TROWB 272
#define TILEB (128 * TROWB)          // 34816
#define XS_B  0
#define Y0_B  TILEB
#define Y1_B  (2 * TILEB)
#define YN_B  (3 * TILEB)            // 104448, 2048 floats
#define XN_B  (YN_B + 8192)          // 112640, 128 floats
#define MB_B  (XN_B + 512)           // 113152, two 8B mbarriers
#define SM_BYTES (MB_B + 64)
#define YTILE_BYTES 32768            // 128 rows x 256B payload per Y tile

// Scratch
__device__ __half       g_xh[BB * NN * DD];   // 16 MB
__device__ __half       g_yh[BB * MM * DD];   // 16 MB
__device__ float        g_xn[BB * NN];
__device__ float        g_yn[BB * MM];
__device__ unsigned int g_rowMin[BB * NN];
__device__ unsigned int g_colMin[BB * MM];
__device__ float        g_partial[256];
__device__ unsigned int g_done = 0;

__device__ __forceinline__ float finf() { return __int_as_float(0x7f800000); }

__device__ __forceinline__ uint32_t smem_u32(const void* p) {
    uint32_t a;
    asm("{ .reg .u64 t; cvta.to.shared.u64 t, %1; cvt.u32.u64 %0, t; }" : "=r"(a) : "l"(p));
    return a;
}
__device__ __forceinline__ void cpasync16(uint32_t dst, const void* src) {
    asm volatile("cp.async.cg.shared.global [%0], [%1], 16;" :: "r"(dst), "l"(src) : "memory");
}
__device__ __forceinline__ void cpasync_wait_all() {
    asm volatile("cp.async.wait_all;" ::: "memory");
}
__device__ __forceinline__ void bulk_cp(uint32_t dst, const void* src, uint32_t bytes,
                                        uint32_t mbar) {
    asm volatile(
        "cp.async.bulk.shared::cta.global.mbarrier::complete_tx::bytes [%0], [%1], %2, [%3];"
        :: "r"(dst), "l"(src), "r"(bytes), "r"(mbar) : "memory");
}
__device__ __forceinline__ void mbar_init(uint32_t a, uint32_t cnt) {
    asm volatile("mbarrier.init.shared.b64 [%0], %1;" :: "r"(a), "r"(cnt) : "memory");
}
__device__ __forceinline__ void mbar_expect_tx(uint32_t a, uint32_t bytes) {
    asm volatile("mbarrier.arrive.expect_tx.shared.b64 _, [%0], %1;"
                 :: "r"(a), "r"(bytes) : "memory");
}
__device__ __forceinline__ void mbar_wait(uint32_t a, uint32_t parity) {
    asm volatile(
        "{\n\t.reg .pred P;\n\t"
        "WL_%=:\n\t"
        "mbarrier.try_wait.parity.acquire.cta.shared::cta.b64 P, [%0], %1, 0x989680;\n\t"
        "@P bra.uni WD_%=;\n\t"
        "bra.uni WL_%=;\n\t"
        "WD_%=:\n\t}"
        :: "r"(a), "r"(parity) : "memory");
}
__device__ __forceinline__ void ldsm_x4(uint32_t* r, uint32_t addr) {
    asm volatile("ldmatrix.sync.aligned.m8n8.x4.shared.b16 {%0,%1,%2,%3}, [%4];"
                 : "=r"(r[0]), "=r"(r[1]), "=r"(r[2]), "=r"(r[3]) : "r"(addr));
}
__device__ __forceinline__ void mma_f16(float* c, const uint32_t* a,
                                        uint32_t b0, uint32_t b1) {
    asm volatile(
        "mma.sync.aligned.m16n8k16.row.col.f32.f16.f16.f32 "
        "{%0,%1,%2,%3}, {%4,%5,%6,%7}, {%8,%9}, {%0,%1,%2,%3};"
        : "+f"(c[0]), "+f"(c[1]), "+f"(c[2]), "+f"(c[3])
        : "r"(a[0]), "r"(a[1]), "r"(a[2]), "r"(a[3]), "r"(b0), "r"(b1));
}

// ---------------------------------------------------------------------------
// Fused fp32->fp16 convert + squared norm + min-init. TWO rows per warp (ILP).
// ---------------------------------------------------------------------------
__global__ void conv_norm_kernel(const float* __restrict__ x,
                                 const float* __restrict__ y) {
    int w    = (blockIdx.x * blockDim.x + threadIdx.x) >> 5;   // 0..65535
    int lane = threadIdx.x & 31;
    const int rowsX = BB * NN;
    int r0 = w * 2;              // rows r0, r0+1 (same tensor: rowsX is even)
    const float* src;
    __half* hdst;
    float* ndst;
    unsigned int* mdst;
    if (r0 < rowsX) {
        src = x + (size_t)r0 * DD; hdst = g_xh + (size_t)r0 * DD;
        ndst = &g_xn[r0]; mdst = &g_rowMin[r0];
    } else {
        int r2 = r0 - rowsX;
        src = y + (size_t)r2 * DD; hdst = g_yh + (size_t)r2 * DD;
        ndst = &g_yn[r2]; mdst = &g_colMin[r2];
    }

    float4 v0 = *(const float4*)(src + lane * 4);
    float4 v1 = *(const float4*)(src + DD + lane * 4);
    __half2 a0 = __floats2half2_rn(v0.x, v0.y);
    __half2 a1 = __floats2half2_rn(v0.z, v0.w);
    __half2 b0 = __floats2half2_rn(v1.x, v1.y);
    __half2 b1 = __floats2half2_rn(v1.z, v1.w);
    uint2 u0, u1;
    u0.x = *reinterpret_cast<uint32_t*>(&a0);
    u0.y = *reinterpret_cast<uint32_t*>(&a1);
    u1.x = *reinterpret_cast<uint32_t*>(&b0);
    u1.y = *reinterpret_cast<uint32_t*>(&b1);
    ((uint2*)hdst)[lane] = u0;
    ((uint2*)(hdst + DD))[lane] = u1;

    float s0 = v0.x * v0.x + v0.y * v0.y + v0.z * v0.z + v0.w * v0.w;
    float s1 = v1.x * v1.x + v1.y * v1.y + v1.z * v1.z + v1.w * v1.w;
    #pragma unroll
    for (int off = 16; off > 0; off >>= 1) {
        s0 += __shfl_xor_sync(0xffffffffu, s0, off);
        s1 += __shfl_xor_sync(0xffffffffu, s1, off);
    }
    if (lane == 0) {
        ndst[0] = s0; ndst[1] = s1;
        mdst[0] = 0x7f800000u; mdst[1] = 0x7f800000u;
    }
}

// ---------------------------------------------------------------------------
// Main: 512 thr, 16 warps (4M x 4N), warp tile 32x32, m16n8k16 f16 mma.
// Y tiles streamed via cp.async.bulk (one 256B copy per row, mbarrier
// completion) to keep the LSU port off the critical path.
// ---------------------------------------------------------------------------
__device__ __forceinline__ void load_tile_h(const __half* __restrict__ g,
                                            uint32_t sbase, int tid) {
    #pragma unroll
    for (int p = 0; p < 4; p++) {
        int c   = p * 512 + tid;
        int row = c >> 4;
        int ch  = c & 15;
        cpasync16(sbase + (uint32_t)(row * TROWB + ch * 16),
                  g + (size_t)row * DD + ch * 8);
    }
}

__device__ __forceinline__ void issue_y_bulk(const __half* __restrict__ gsrc,
                                             uint32_t dst, uint32_t mbar) {
    mbar_expect_tx(mbar, YTILE_BYTES);
    #pragma unroll 4
    for (int r = 0; r < 128; r++)
        bulk_cp(dst + (uint32_t)(r * TROWB), gsrc + (size_t)r * DD, 256, mbar);
}

__global__ __launch_bounds__(512, 1)
void chamfer_mma_kernel() {
    extern __shared__ char sm[];
    const uint32_t sb = smem_u32(sm);

    const int b     = blockIdx.y;
    const int i0    = blockIdx.x * 128;
    const int jbase = blockIdx.z * NJT_JOB;
    const int tid  = threadIdx.x;
    const int lane = tid & 31;
    const int gq   = lane >> 2;
    const int t4   = lane & 3;
    const int wid  = tid >> 5;
    const int wm   = wid & 3;
    const int wn   = wid >> 2;
    const int m0   = wm * 32;
    const int n0   = wn * 32;

    const int lm_row = ((lane >> 3) & 1) * 8 + (lane & 7);
    const int lm_k   = (lane >> 4) * 8;

    const __half* xb = g_xh + (size_t)b * NN * DD;
    const __half* yb = g_yh + (size_t)b * MM * DD;

    // ---- prologue ----
    if (tid == 0) {
        mbar_init(sb + MB_B, 1);
        mbar_init(sb + MB_B + 8, 1);
    }
    load_tile_h(xb + (size_t)i0 * DD, sb + XS_B, tid);
    cpasync16(sb + YN_B + tid * 16, g_yn + (size_t)b * MM + tid * 4);
    if (tid < 32)
        cpasync16(sb + XN_B + tid * 16, g_xn + (size_t)b * NN + i0 + tid * 4);
    cpasync_wait_all();
    __syncthreads();               // mbar init + X/norm data visible
    if (tid == 0)
        issue_y_bulk(yb + (size_t)jbase * 128 * DD, sb + Y0_B, sb + MB_B);

    const float* yn_s = (const float*)(sm + YN_B);
    const float* xn_s = (const float*)(sm + XN_B);

    const uint32_t a_addr0 = sb + XS_B + (uint32_t)((m0 + lm_row) * TROWB + lm_k * 2);
    const uint32_t a_addr1 = a_addr0 + 16 * TROWB;

    float xnr[2][2];
    #pragma unroll
    for (int mt = 0; mt < 2; mt++) {
        xnr[mt][0] = xn_s[m0 + mt * 16 + gq];
        xnr[mt][1] = xn_s[m0 + mt * 16 + gq + 8];
    }
    float rmin[2][2];
    rmin[0][0] = rmin[0][1] = rmin[1][0] = rmin[1][1] = finf();

    float accA[2][4][4], accB[2][4][4];

    // 1/8th of the epilogue for a finished tile (chunk c = (nt, e)); j0p global
    auto epi_chunk = [&](float (&accP)[2][4][4], int j0p, int c) {
        const int nt = c >> 1, e = c & 1;
        const int col = j0p + n0 + nt * 8 + 2 * t4 + e;
        float yc  = yn_s[col];
        float s00 = fmaf(-2.0f, accP[0][nt][e],     xnr[0][0] + yc);
        float s01 = fmaf(-2.0f, accP[0][nt][e + 2], xnr[0][1] + yc);
        float s10 = fmaf(-2.0f, accP[1][nt][e],     xnr[1][0] + yc);
        float s11 = fmaf(-2.0f, accP[1][nt][e + 2], xnr[1][1] + yc);
        rmin[0][0] = fminf(rmin[0][0], s00);
        rmin[0][1] = fminf(rmin[0][1], s01);
        rmin[1][0] = fminf(rmin[1][0], s10);
        rmin[1][1] = fminf(rmin[1][1], s11);
        float cmv = fminf(fminf(s00, s01), fminf(s10, s11));
        cmv = fminf(cmv, __shfl_xor_sync(0xffffffffu, cmv, 4));
        cmv = fminf(cmv, __shfl_xor_sync(0xffffffffu, cmv, 8));
        cmv = fminf(cmv, __shfl_xor_sync(0xffffffffu, cmv, 16));
        if (gq == 0)
            atomicMin(&g_colMin[(size_t)b * MM + col],
                      __float_as_uint(fmaxf(cmv, 0.0f)));
    };

    // one local j-tile t: MMAs into accC; epilogue chunks on accP (tile t-1)
    auto do_tile = [&](int t, float (&accC)[2][4][4], float (&accP)[2][4][4],
                       bool epi) {
        if (t > 0) __syncthreads();   // all warps done reading buffer (t+1)&1
        if (t + 1 < NJT_JOB && tid == 0) {
            uint32_t buf = ((t + 1) & 1) ? (sb + Y1_B) : (sb + Y0_B);
            issue_y_bulk(yb + (size_t)(jbase + t + 1) * 128 * DD, buf,
                         sb + MB_B + ((t + 1) & 1) * 8);
        }
        mbar_wait(sb + MB_B + (t & 1) * 8, (uint32_t)((t >> 1) & 1));

        const uint32_t Ysb = sb + ((t & 1) ? Y1_B : Y0_B);
        const uint32_t b_addr0 = Ysb + (uint32_t)((n0 + lm_row) * TROWB + lm_k * 2);
        const uint32_t b_addr1 = b_addr0 + 16 * TROWB;

        #pragma unroll
        for (int mt = 0; mt < 2; mt++)
            #pragma unroll
            for (int nt = 0; nt < 4; nt++)
                #pragma unroll
                for (int e = 0; e < 4; e++) accC[mt][nt][e] = 0.0f;

        const int j0p = (jbase + t - 1) * 128;
        #pragma unroll
        for (int ks = 0; ks < 8; ks++) {
            const uint32_t ko = (uint32_t)(ks * 32);
            uint32_t a[2][4], bfr[2][4];
            ldsm_x4(a[0], a_addr0 + ko);
            ldsm_x4(a[1], a_addr1 + ko);
            ldsm_x4(bfr[0], b_addr0 + ko);
            ldsm_x4(bfr[1], b_addr1 + ko);
            #pragma unroll
            for (int mt = 0; mt < 2; mt++)
                #pragma unroll
                for (int nt = 0; nt < 4; nt++)
                    mma_f16(accC[mt][nt], a[mt], bfr[nt >> 1][nt & 1],
                            bfr[nt >> 1][(nt & 1) + 2]);
            if (epi) epi_chunk(accP, j0p, ks);
        }
    };

    for (int tt = 0; tt < NJT_JOB; tt += 2) {
        do_tile(tt,     accA, accB, tt > 0);
        do_tile(tt + 1, accB, accA, true);
    }
    // epilogue for the last tile (accumulators in accB)
    #pragma unroll
    for (int c = 0; c < 8; c++) epi_chunk(accB, (jbase + NJT_JOB - 1) * 128, c);

    // ---- row-min flush ----
    #pragma unroll
    for (int mt = 0; mt < 2; mt++)
        #pragma unroll
        for (int e = 0; e < 2; e++) {
            float v = rmin[mt][e];
            v = fminf(v, __shfl_xor_sync(0xffffffffu, v, 1));
            v = fminf(v, __shfl_xor_sync(0xffffffffu, v, 2));
            if (t4 == 0) {
                int row = i0 + m0 + mt * 16 + gq + e * 8;
                atomicMin(&g_rowMin[(size_t)b * NN + row],
                          __float_as_uint(fmaxf(v, 0.0f)));
            }
        }
}

// ---------------------------------------------------------------------------
// Fused two-stage reduce (threadfence pattern; counter wraps -> replay safe).
// ---------------------------------------------------------------------------
__global__ void reduce_kernel(float* __restrict__ out) {
    __shared__ float s[256];
    __shared__ bool amLast;
    const int tid  = threadIdx.x;
    const int base = blockIdx.x * 512;
    float v = 0.0f;
    #pragma unroll
    for (int o = 0; o < 512; o += 256) {
        int idx = base + o + tid;
        unsigned u = (idx < BB * NN) ? g_rowMin[idx] : g_colMin[idx - BB * NN];
        v += sqrtf(__uint_as_float(u));
    }
    s[tid] = v;
    __syncthreads();
    for (int st = 128; st > 0; st >>= 1) {
        if (tid < st) s[tid] += s[tid + st];
        __syncthreads();
    }
    if (tid == 0) {
        g_partial[blockIdx.x] = s[0];
        __threadfence();
        unsigned prev = atomicInc(&g_done, gridDim.x - 1);
        amLast = (prev == gridDim.x - 1);
    }
    __syncthreads();
    if (amLast) {
        float p = ((volatile float*)g_partial)[tid];
        s[tid] = p;
        __syncthreads();
        for (int st = 128; st > 0; st >>= 1) {
            if (tid < st) s[tid] += s[tid + st];
            __syncthreads();
        }
        if (tid == 0) out[0] = s[0];
    }
}

// ---------------------------------------------------------------------------
extern "C" void kernel_launch(void* const* d_in, const int* in_sizes, int n_in,
                              void* d_out, int out_size) {
    const float* x = (const float*)d_in[0];
    const float* y = (const float*)d_in[1];
    float* out = (float*)d_out;

    cudaFuncSetAttribute(chamfer_mma_kernel,
                         cudaFuncAttributeMaxDynamicSharedMemorySize, SM_BYTES);

    conv_norm_kernel<<<(BB * (NN + MM) / 2) / 8, 256>>>(x, y);
    chamfer_mma_kernel<<<dim3(NN / 128, BB, 2), 512, SM_BYTES>>>();
    reduce_kernel<<<256, 256>>>(out);
}

// round 16
// speedup vs baseline: 2.0700x; 2.0700x over previous
#include <cuda_runtime.h>
#include <cuda_fp16.h>
#include <cstdint>

#define BB 32
#define NN 2048
#define MM 2048
#define DD 128

#define NJT_JOB 8         // j-tiles per job (half sweep)

// fp16 tiles in smem: 128 rows x 128 halfs, row stride 272 bytes (16B pad)
#define TROWB 272
#define TILEB (128 * TROWB)          // 34816
#define XS_B  0
#define Y0_B  TILEB
#define Y2_B  (3 * TILEB)            // third Y buffer base (Y0,Y1,Y2)
#define YN_B  (4 * TILEB)            // 139264, 2048 floats
#define XN_B  (YN_B + 8192)          // 147456, 128 floats
#define SM_BYTES (XN_B + 512)        // 147968

// Scratch
__device__ __half       g_xh[BB * NN * DD];   // 16 MB
__device__ __half       g_yh[BB * MM * DD];   // 16 MB
__device__ float        g_xn[BB * NN];
__device__ float        g_yn[BB * MM];
__device__ unsigned int g_rowMin[BB * NN];
__device__ unsigned int g_colMin[BB * MM];
__device__ float        g_partial[256];
__device__ unsigned int g_done = 0;

__device__ __forceinline__ float finf() { return __int_as_float(0x7f800000); }

__device__ __forceinline__ uint32_t smem_u32(const void* p) {
    uint32_t a;
    asm("{ .reg .u64 t; cvta.to.shared.u64 t, %1; cvt.u32.u64 %0, t; }" : "=r"(a) : "l"(p));
    return a;
}
__device__ __forceinline__ void cpasync16(uint32_t dst, const void* src) {
    asm volatile("cp.async.cg.shared.global [%0], [%1], 16;" :: "r"(dst), "l"(src) : "memory");
}
__device__ __forceinline__ void cpasync_commit() {
    asm volatile("cp.async.commit_group;" ::: "memory");
}
__device__ __forceinline__ void cpasync_wait1() {
    asm volatile("cp.async.wait_group 1;" ::: "memory");
}
__device__ __forceinline__ void ldsm_x4(uint32_t* r, uint32_t addr) {
    asm volatile("ldmatrix.sync.aligned.m8n8.x4.shared.b16 {%0,%1,%2,%3}, [%4];"
                 : "=r"(r[0]), "=r"(r[1]), "=r"(r[2]), "=r"(r[3]) : "r"(addr));
}
__device__ __forceinline__ void mma_f16(float* c, const uint32_t* a,
                                        uint32_t b0, uint32_t b1) {
    asm volatile(
        "mma.sync.aligned.m16n8k16.row.col.f32.f16.f16.f32 "
        "{%0,%1,%2,%3}, {%4,%5,%6,%7}, {%8,%9}, {%0,%1,%2,%3};"
        : "+f"(c[0]), "+f"(c[1]), "+f"(c[2]), "+f"(c[3])
        : "r"(a[0]), "r"(a[1]), "r"(a[2]), "r"(a[3]), "r"(b0), "r"(b1));
}

// ---------------------------------------------------------------------------
// Fused fp32->fp16 convert + squared norm + min-init. TWO rows per warp (ILP).
// ---------------------------------------------------------------------------
__global__ void conv_norm_kernel(const float* __restrict__ x,
                                 const float* __restrict__ y) {
    int w    = (blockIdx.x * blockDim.x + threadIdx.x) >> 5;   // 0..65535
    int lane = threadIdx.x & 31;
    const int rowsX = BB * NN;
    int r0 = w * 2;
    const float* src;
    __half* hdst;
    float* ndst;
    unsigned int* mdst;
    if (r0 < rowsX) {
        src = x + (size_t)r0 * DD; hdst = g_xh + (size_t)r0 * DD;
        ndst = &g_xn[r0]; mdst = &g_rowMin[r0];
    } else {
        int r2 = r0 - rowsX;
        src = y + (size_t)r2 * DD; hdst = g_yh + (size_t)r2 * DD;
        ndst = &g_yn[r2]; mdst = &g_colMin[r2];
    }

    float4 v0 = *(const float4*)(src + lane * 4);
    float4 v1 = *(const float4*)(src + DD + lane * 4);
    __half2 a0 = __floats2half2_rn(v0.x, v0.y);
    __half2 a1 = __floats2half2_rn(v0.z, v0.w);
    __half2 b0 = __floats2half2_rn(v1.x, v1.y);
    __half2 b1 = __floats2half2_rn(v1.z, v1.w);
    uint2 u0, u1;
    u0.x = *reinterpret_cast<uint32_t*>(&a0);
    u0.y = *reinterpret_cast<uint32_t*>(&a1);
    u1.x = *reinterpret_cast<uint32_t*>(&b0);
    u1.y = *reinterpret_cast<uint32_t*>(&b1);
    ((uint2*)hdst)[lane] = u0;
    ((uint2*)(hdst + DD))[lane] = u1;

    float s0 = v0.x * v0.x + v0.y * v0.y + v0.z * v0.z + v0.w * v0.w;
    float s1 = v1.x * v1.x + v1.y * v1.y + v1.z * v1.z + v1.w * v1.w;
    #pragma unroll
    for (int off = 16; off > 0; off >>= 1) {
        s0 += __shfl_xor_sync(0xffffffffu, s0, off);
        s1 += __shfl_xor_sync(0xffffffffu, s1, off);
    }
    if (lane == 0) {
        ndst[0] = s0; ndst[1] = s1;
        mdst[0] = 0x7f800000u; mdst[1] = 0x7f800000u;
    }
}

// ---------------------------------------------------------------------------
// Main: 512 thr, 16 warps (4M x 4N), warp tile 32x32, m16n8k16 f16 mma.
// Triple-buffered Y (LDGSTS, wait_group 1 -> zero exposed load latency).
// Epilogue of tile t-1 interleaved into tile t's k-loop (acc double buffer).
// ---------------------------------------------------------------------------
__device__ __forceinline__ void load_tile_h(const __half* __restrict__ g,
                                            uint32_t sbase, int tid) {
    #pragma unroll
    for (int p = 0; p < 4; p++) {
        int c   = p * 512 + tid;
        int row = c >> 4;
        int ch  = c & 15;
        cpasync16(sbase + (uint32_t)(row * TROWB + ch * 16),
                  g + (size_t)row * DD + ch * 8);
    }
}

__global__ __launch_bounds__(512, 1)
void chamfer_mma_kernel() {
    extern __shared__ char sm[];
    const uint32_t sb = smem_u32(sm);

    const int b     = blockIdx.y;
    const int i0    = blockIdx.x * 128;
    const int jbase = blockIdx.z * NJT_JOB;
    const int tid  = threadIdx.x;
    const int lane = tid & 31;
    const int gq   = lane >> 2;
    const int t4   = lane & 3;
    const int wid  = tid >> 5;
    const int wm   = wid & 3;
    const int wn   = wid >> 2;
    const int m0   = wm * 32;
    const int n0   = wn * 32;

    const int lm_row = ((lane >> 3) & 1) * 8 + (lane & 7);
    const int lm_k   = (lane >> 4) * 8;

    const __half* xb = g_xh + (size_t)b * NN * DD;
    const __half* yb = g_yh + (size_t)b * MM * DD;

    // ---- prologue: group0 = X + norms + Y0, group1 = Y1 ----
    load_tile_h(xb + (size_t)i0 * DD, sb + XS_B, tid);
    cpasync16(sb + YN_B + tid * 16, g_yn + (size_t)b * MM + tid * 4);
    if (tid < 32)
        cpasync16(sb + XN_B + tid * 16, g_xn + (size_t)b * NN + i0 + tid * 4);
    load_tile_h(yb + (size_t)jbase * 128 * DD, sb + Y0_B, tid);
    cpasync_commit();
    load_tile_h(yb + (size_t)(jbase + 1) * 128 * DD, sb + Y0_B + TILEB, tid);
    cpasync_commit();
    cpasync_wait1();               // group0 (X, norms, Y0) complete
    __syncthreads();

    const float* yn_s = (const float*)(sm + YN_B);
    const float* xn_s = (const float*)(sm + XN_B);

    const uint32_t a_addr0 = sb + XS_B + (uint32_t)((m0 + lm_row) * TROWB + lm_k * 2);
    const uint32_t a_addr1 = a_addr0 + 16 * TROWB;

    float xnr[2][2];
    #pragma unroll
    for (int mt = 0; mt < 2; mt++) {
        xnr[mt][0] = xn_s[m0 + mt * 16 + gq];
        xnr[mt][1] = xn_s[m0 + mt * 16 + gq + 8];
    }
    float rmin[2][2];
    rmin[0][0] = rmin[0][1] = rmin[1][0] = rmin[1][1] = finf();

    float accA[2][4][4], accB[2][4][4];

    // 1/8th of the epilogue for a finished tile (chunk c = (nt, e)); j0p global
    auto epi_chunk = [&](float (&accP)[2][4][4], int j0p, int c) {
        const int nt = c >> 1, e = c & 1;
        const int col = j0p + n0 + nt * 8 + 2 * t4 + e;
        float yc  = yn_s[col];
        float s00 = fmaf(-2.0f, accP[0][nt][e],     xnr[0][0] + yc);
        float s01 = fmaf(-2.0f, accP[0][nt][e + 2], xnr[0][1] + yc);
        float s10 = fmaf(-2.0f, accP[1][nt][e],     xnr[1][0] + yc);
        float s11 = fmaf(-2.0f, accP[1][nt][e + 2], xnr[1][1] + yc);
        rmin[0][0] = fminf(rmin[0][0], s00);
        rmin[0][1] = fminf(rmin[0][1], s01);
        rmin[1][0] = fminf(rmin[1][0], s10);
        rmin[1][1] = fminf(rmin[1][1], s11);
        float cmv = fminf(fminf(s00, s01), fminf(s10, s11));
        cmv = fminf(cmv, __shfl_xor_sync(0xffffffffu, cmv, 4));
        cmv = fminf(cmv, __shfl_xor_sync(0xffffffffu, cmv, 8));
        cmv = fminf(cmv, __shfl_xor_sync(0xffffffffu, cmv, 16));
        if (gq == 0)
            atomicMin(&g_colMin[(size_t)b * MM + col],
                      __float_as_uint(fmaxf(cmv, 0.0f)));
    };

    // one j-tile: MMAs from ycur into accC; epilogue chunks on accP (tile t-1)
    auto do_tile = [&](int t, float (&accC)[2][4][4], float (&accP)[2][4][4],
                       bool epi, uint32_t ycur, uint32_t yld) {
        if (t > 0) { cpasync_wait1(); __syncthreads(); }
        if (t + 2 < NJT_JOB) {
            load_tile_h(yb + (size_t)(jbase + t + 2) * 128 * DD, yld, tid);
            cpasync_commit();
        }
        const uint32_t b_addr0 = ycur + (uint32_t)((n0 + lm_row) * TROWB + lm_k * 2);
        const uint32_t b_addr1 = b_addr0 + 16 * TROWB;

        #pragma unroll
        for (int mt = 0; mt < 2; mt++)
            #pragma unroll
            for (int nt = 0; nt < 4; nt++)
                #pragma unroll
                for (int e = 0; e < 4; e++) accC[mt][nt][e] = 0.0f;

        const int j0p = (jbase + t - 1) * 128;
        #pragma unroll
        for (int ks = 0; ks < 8; ks++) {
            const uint32_t ko = (uint32_t)(ks * 32);
            uint32_t a[2][4], bfr[2][4];
            ldsm_x4(a[0], a_addr0 + ko);
            ldsm_x4(a[1], a_addr1 + ko);
            ldsm_x4(bfr[0], b_addr0 + ko);
            ldsm_x4(bfr[1], b_addr1 + ko);
            #pragma unroll
            for (int mt = 0; mt < 2; mt++)
                #pragma unroll
                for (int nt = 0; nt < 4; nt++)
                    mma_f16(accC[mt][nt], a[mt], bfr[nt >> 1][nt & 1],
                            bfr[nt >> 1][(nt & 1) + 2]);
            if (epi) epi_chunk(accP, j0p, ks);
        }
    };

    // rotating Y buffer pointers: ycur tracks tile t, yld tracks tile t+2
    auto rot = [&](uint32_t v) {
        return (v == sb + Y2_B) ? (sb + Y0_B) : (v + (uint32_t)TILEB);
    };
    uint32_t ycur = sb + Y0_B;
    uint32_t yld  = sb + Y2_B;

    for (int tt = 0; tt < NJT_JOB; tt += 2) {
        do_tile(tt,     accA, accB, tt > 0, ycur, yld);
        ycur = rot(ycur); yld = rot(yld);
        do_tile(tt + 1, accB, accA, true, ycur, yld);
        ycur = rot(ycur); yld = rot(yld);
    }
    // epilogue for the last tile (accumulators in accB)
    #pragma unroll
    for (int c = 0; c < 8; c++) epi_chunk(accB, (jbase + NJT_JOB - 1) * 128, c);

    // ---- row-min flush ----
    #pragma unroll
    for (int mt = 0; mt < 2; mt++)
        #pragma unroll
        for (int e = 0; e < 2; e++) {
            float v = rmin[mt][e];
            v = fminf(v, __shfl_xor_sync(0xffffffffu, v, 1));
            v = fminf(v, __shfl_xor_sync(0xffffffffu, v, 2));
            if (t4 == 0) {
                int row = i0 + m0 + mt * 16 + gq + e * 8;
                atomicMin(&g_rowMin[(size_t)b * NN + row],
                          __float_as_uint(fmaxf(v, 0.0f)));
            }
        }
}

// ---------------------------------------------------------------------------
// Fused two-stage reduce (threadfence pattern; counter wraps -> replay safe).
// ---------------------------------------------------------------------------
__global__ void reduce_kernel(float* __restrict__ out) {
    __shared__ float s[256];
    __shared__ bool amLast;
    const int tid  = threadIdx.x;
    const int base = blockIdx.x * 512;
    float v = 0.0f;
    #pragma unroll
    for (int o = 0; o < 512; o += 256) {
        int idx = base + o + tid;
        unsigned u = (idx < BB * NN) ? g_rowMin[idx] : g_colMin[idx - BB * NN];
        v += sqrtf(__uint_as_float(u));
    }
    s[tid] = v;
    __syncthreads();
    for (int st = 128; st > 0; st >>= 1) {
        if (tid < st) s[tid] += s[tid + st];
        __syncthreads();
    }
    if (tid == 0) {
        g_partial[blockIdx.x] = s[0];
        __threadfence();
        unsigned prev = atomicInc(&g_done, gridDim.x - 1);
        amLast = (prev == gridDim.x - 1);
    }
    __syncthreads();
    if (amLast) {
        float p = ((volatile float*)g_partial)[tid];
        s[tid] = p;
        __syncthreads();
        for (int st = 128; st > 0; st >>= 1) {
            if (tid < st) s[tid] += s[tid + st];
            __syncthreads();
        }
        if (tid == 0) out[0] = s[0];
    }
}

// ---------------------------------------------------------------------------
extern "C" void kernel_launch(void* const* d_in, const int* in_sizes, int n_in,
                              void* d_out, int out_size) {
    const float* x = (const float*)d_in[0];
    const float* y = (const float*)d_in[1];
    float* out = (float*)d_out;

    cudaFuncSetAttribute(chamfer_mma_kernel,
                         cudaFuncAttributeMaxDynamicSharedMemorySize, SM_BYTES);

    conv_norm_kernel<<<(BB * (NN + MM) / 2) / 8, 256>>>(x, y);
    chamfer_mma_kernel<<<dim3(NN / 128, BB, 2), 512, SM_BYTES>>>();
    reduce_kernel<<<256, 256>>>(out);
}